// round 15
// baseline (speedup 1.0000x reference)
#include <cuda_runtime.h>
#include <cuda_bf16.h>
#include <cuda_fp16.h>
#include <cstdint>

// ---------------------------------------------------------------------------
// TransformerConv: N=100000 nodes, E=1600000 edges, IN=128, H=4, C=32, ED=16
//
// sm_103 base target (NO tcgen05 — harness PTX is .target sm_103):
//   1) prep_kernel : W{q,k,v,skip}->fp16 [512x128] + Wg fold + zero d_count
//   2) fill_buckets: bucket {edge,src} pairs by destination node
//   3) proj_mma    : fp16 mma.sync, M=256/512thr, cp.async double-buffered B
//   4) agg_kernel  : warp-per-dst-node, 2 edges/step; kv stored interleaved
//                    [k8|v8] per lane -> ONE 256-bit evict_last load per edge
//                    per lane; skip+g in fp16 (-114MB DRAM)
// ---------------------------------------------------------------------------

#define MAXN 100096
#define BCAP 96   // per-node bucket capacity (Poisson(16) max ~36; 96 is safe)

__device__ __half d_sh[MAXN * 128];    // skip fp16
__device__ __half d_gh[MAXN * 64];     // g fp16
__device__ __half d_qh[MAXN * 128];    // q fp16, ch-major
// kv interleaved: per node 512B = 16 lane-groups of 32B: [k ch8 | v ch8]
__device__ __half d_kvh[MAXN * 256];
__device__ int    d_count[MAXN];
__device__ int2   d_bucket[MAXN * BCAP];  // {edge id, src node}
__device__ __half d_B[576 * 128];      // W^T fp16, n-major rows, k cols (+Wg)
__device__ float  d_bg[64];            // bias for folded g projection

// ============================ helpers ======================================
__device__ __forceinline__ uint32_t smem_u32(const void* p) {
    uint32_t a;
    asm("{ .reg .u64 t; cvta.to.shared.u64 t, %1; cvt.u32.u64 %0, t; }"
        : "=r"(a) : "l"(p));
    return a;
}
__device__ __forceinline__ void ldm_x4(uint32_t& r0, uint32_t& r1,
                                       uint32_t& r2, uint32_t& r3, uint32_t addr) {
    asm volatile("ldmatrix.sync.aligned.m8n8.x4.shared.b16 {%0,%1,%2,%3}, [%4];"
                 : "=r"(r0), "=r"(r1), "=r"(r2), "=r"(r3) : "r"(addr));
}
__device__ __forceinline__ void mma_f16(float* c, const uint32_t* a,
                                        uint32_t b0, uint32_t b1) {
    asm volatile(
        "mma.sync.aligned.m16n8k16.row.col.f32.f16.f16.f32 "
        "{%0,%1,%2,%3}, {%4,%5,%6,%7}, {%8,%9}, {%0,%1,%2,%3};"
        : "+f"(c[0]), "+f"(c[1]), "+f"(c[2]), "+f"(c[3])
        : "r"(a[0]), "r"(a[1]), "r"(a[2]), "r"(a[3]), "r"(b0), "r"(b1));
}
__device__ __forceinline__ void cp_async16(uint32_t saddr, const void* gptr) {
    asm volatile("cp.async.ca.shared.global [%0], [%1], 16;"
                 :: "r"(saddr), "l"(gptr));
}
__device__ __forceinline__ void cp_commit() {
    asm volatile("cp.async.commit_group;");
}
__device__ __forceinline__ void cp_wait0() {
    asm volatile("cp.async.wait_group 0;");
}
// 256-bit kv gather, L2 evict_last (v4.b64 form required by this ptxas)
__device__ __forceinline__ ulonglong4 ldg256_keep(const void* p) {
    ulonglong4 r;
    asm volatile("ld.global.nc.L2::evict_last.v4.b64 {%0,%1,%2,%3}, [%4];"
                 : "=l"(r.x), "=l"(r.y), "=l"(r.z), "=l"(r.w) : "l"(p));
    return r;
}
// streaming policies for ea / buckets
__device__ __forceinline__ unsigned long long policy_stream() {
    unsigned long long p;
    asm("createpolicy.fractional.L2::evict_first.b64 %0, 1.0;" : "=l"(p));
    return p;
}
__device__ __forceinline__ float4 ldg_hint4f(const void* p, unsigned long long pol) {
    float4 r;
    asm volatile("ld.global.nc.L2::cache_hint.v4.f32 {%0,%1,%2,%3}, [%4], %5;"
                 : "=f"(r.x), "=f"(r.y), "=f"(r.z), "=f"(r.w)
                 : "l"(p), "l"(pol));
    return r;
}
__device__ __forceinline__ int2 ldg_hint2i(const void* p, unsigned long long pol) {
    int2 r;
    asm volatile("ld.global.nc.L2::cache_hint.v2.u32 {%0,%1}, [%2], %3;"
                 : "=r"(r.x), "=r"(r.y) : "l"(p), "l"(pol));
    return r;
}
__device__ __forceinline__ void stg_stream4f(void* p, float4 v) {
    asm volatile("st.global.cs.v4.f32 [%0], {%1,%2,%3,%4};"
                 :: "l"(p), "f"(v.x), "f"(v.y), "f"(v.z), "f"(v.w));
}

// ---------------------------------------------------------------------------
// prep: blocks [0,256): W pack; [256,288): Wg fold; [288,...): zero d_count
// ---------------------------------------------------------------------------
__global__ void __launch_bounds__(256)
prep_kernel(const float* __restrict__ Wq, const float* __restrict__ Wk,
            const float* __restrict__ Wv, const float* __restrict__ Ws,
            const float* __restrict__ We, const float* __restrict__ bq)
{
    int b = blockIdx.x, tid = threadIdx.x;
    if (b < 256) {
        int i = b * 256 + tid;               // 65536 elements
        int k = i >> 9, nn = i & 511;
        int w = nn >> 7, c = nn & 127;
        const float* W = (w == 0) ? Wq : (w == 1) ? Wk : (w == 2) ? Wv : Ws;
        d_B[nn * 128 + k] = __float2half_rn(W[k * 128 + c]);
    } else if (b < 288) {
        int t = (b - 256) * 256 + tid;       // 8192: (i, o)
        int i = t >> 6, o = t & 63;
        int h = o >> 4, d = o & 15;
        float s = 0.f;
#pragma unroll
        for (int c = 0; c < 32; ++c)
            s += Wq[i * 128 + h * 32 + c] * We[d * 128 + h * 32 + c];
        d_B[(512 + o) * 128 + i] = __float2half_rn(s);
        if (i == 0) {
            float sb = 0.f;
#pragma unroll
            for (int c = 0; c < 32; ++c)
                sb += bq[h * 32 + c] * We[d * 128 + h * 32 + c];
            d_bg[o] = sb;
        }
    } else {
        int i = (b - 288) * 256 + tid;
        if (i < MAXN) d_count[i] = 0;
    }
}

// ---------------------------------------------------------------------------
// Edge bucketing: store {edge, src} pairs
// ---------------------------------------------------------------------------
__global__ void __launch_bounds__(256)
fill_buckets(const int* __restrict__ row, const int* __restrict__ colv, int e)
{
    int i = blockIdx.x * blockDim.x + threadIdx.x;
    if (i >= e) return;
    int dst = row[i];
    int src = colv[i];
    int pos = atomicAdd(&d_count[dst], 1);
    if (pos < BCAP) d_bucket[dst * BCAP + pos] = make_int2(i, src);
}

// ---------------------------------------------------------------------------
// Projection: M=256 tile / 512 threads; B double-buffered via cp.async.
// ---------------------------------------------------------------------------
#define ASTR 136
#define PROJ_SMEM ((256 + 256) * ASTR * 2)

template <int NF>
__device__ __forceinline__ void mma_chunk(uint32_t uA, uint32_t uB,
                                          float (*acc)[4], int wid, int lane)
{
    uint32_t a_row = (uint32_t)(wid * 16 + (lane & 15));
    uint32_t a_koff = (uint32_t)((lane >> 4) * 8);
    uint32_t b_sub = (uint32_t)((lane >> 4) & 1);
    uint32_t b_kh  = (uint32_t)((lane >> 3) & 1);
    uint32_t b_rin = (uint32_t)(lane & 7);
#pragma unroll
    for (int ks = 0; ks < 8; ++ks) {
        uint32_t a[4];
        ldm_x4(a[0], a[1], a[2], a[3],
               uA + (a_row * ASTR + ks * 16 + a_koff) * 2);
#pragma unroll
        for (int p = 0; p < NF / 2; ++p) {
            uint32_t brow = (2 * p + b_sub) * 8 + b_rin;
            uint32_t b0, b1, b2, b3;
            ldm_x4(b0, b1, b2, b3,
                   uB + (brow * ASTR + ks * 16 + b_kh * 8) * 2);
            mma_f16(acc[2 * p], a, b0, b1);
            mma_f16(acc[2 * p + 1], a, b2, b3);
        }
    }
}

__device__ __forceinline__ void stage_B_async(ushort* sB, int nc, int NF, int tid)
{
    uint32_t ub = smem_u32(sB);
    for (int i = tid; i < NF * 8 * 16; i += 512) {
        int r = i >> 4, c8 = i & 15;
        cp_async16(ub + (uint32_t)(r * ASTR + c8 * 8) * 2,
                   &d_B[(nc * 128 + r) * 128 + c8 * 8]);
    }
    cp_commit();
}

__global__ void __launch_bounds__(512, 1)
proj_mma(const float* __restrict__ x,
         const float* __restrict__ bq, const float* __restrict__ bk,
         const float* __restrict__ bv, const float* __restrict__ bs,
         int n)
{
    extern __shared__ __align__(16) char smem[];
    ushort* sA  = (ushort*)smem;                // [256][ASTR]
    ushort* sB0 = sA + 256 * ASTR;              // [128][ASTR]
    ushort* sB1 = sB0 + 128 * ASTR;             // [128][ASTR]

    int tid = threadIdx.x, lane = tid & 31, wid = tid >> 5;
    int row0 = blockIdx.x * 256;

    stage_B_async(sB0, 0, 16, tid);

    for (int i = tid; i < 256 * 32; i += 512) {
        int r = i >> 5, c4 = i & 31;
        int node = row0 + r;
        float4 xv = (node < n) ? *(const float4*)&x[node * 128 + c4 * 4]
                               : make_float4(0.f, 0.f, 0.f, 0.f);
        __half2 h01 = __floats2half2_rn(xv.x, xv.y);
        __half2 h23 = __floats2half2_rn(xv.z, xv.w);
        *(uint2*)&sA[r * ASTR + c4 * 4] =
            make_uint2(*(uint32_t*)&h01, *(uint32_t*)&h23);
    }

    uint32_t uA = smem_u32(sA);
    ushort* sBcur = sB0;
    ushort* sBnxt = sB1;
    ushort* kvs = (ushort*)d_kvh;

    for (int nc = 0; nc < 5; ++nc) {
        cp_wait0();
        __syncthreads();
        if (nc < 4)
            stage_B_async(sBnxt, nc + 1, (nc + 1 == 4) ? 8 : 16, tid);

        float acc[16][4];
#pragma unroll
        for (int f = 0; f < 16; ++f)
#pragma unroll
            for (int j = 0; j < 4; ++j) acc[f][j] = 0.f;

        uint32_t uB = smem_u32(sBcur);
        if (nc == 4) mma_chunk<8>(uA, uB, acc, wid, lane);
        else         mma_chunk<16>(uA, uB, acc, wid, lane);

        int r_base = row0 + wid * 16 + (lane >> 2);
        if (nc == 4) {
#pragma unroll
            for (int nf = 0; nf < 8; ++nf) {
                int cn = nf * 8 + (lane & 3) * 2;
                float b0 = d_bg[cn], b1 = d_bg[cn + 1];
#pragma unroll
                for (int half = 0; half < 2; ++half) {
                    int node = r_base + half * 8;
                    if (node >= n) continue;
                    __half2 hh = __floats2half2_rn(acc[nf][half * 2] + b0,
                                                   acc[nf][half * 2 + 1] + b1);
                    *(__half2*)&d_gh[node * 64 + cn] = hh;
                }
            }
        } else {
            const float* bias = (nc == 0) ? bq : (nc == 1) ? bk : (nc == 2) ? bv : bs;
#pragma unroll
            for (int nf = 0; nf < 16; ++nf) {
                int cn = nf * 8 + (lane & 3) * 2;
                float b0 = __ldg(&bias[cn]), b1 = __ldg(&bias[cn + 1]);
#pragma unroll
                for (int half = 0; half < 2; ++half) {
                    int node = r_base + half * 8;
                    if (node >= n) continue;
                    float v0 = acc[nf][half * 2 + 0] + b0;
                    float v1 = acc[nf][half * 2 + 1] + b1;
                    __half2 hh = __floats2half2_rn(v0, v1);
                    if (nc == 3) {
                        *(__half2*)&d_sh[node * 128 + cn] = hh;
                    } else if (nc == 0) {
                        *(__half2*)&d_qh[node * 128 + cn] = hh;
                    } else {
                        // interleaved kv: lane-group = cn>>3; k at +0, v at +8
                        uint32_t idx = (uint32_t)node * 256 + ((cn >> 3) << 4)
                                     + (cn & 7) + (nc == 2 ? 8 : 0);
                        *(uint32_t*)&kvs[idx] = *(uint32_t*)&hh;
                    }
                }
            }
        }
        ushort* t = sBcur; sBcur = sBnxt; sBnxt = t;
        __syncthreads();
    }
}

// ---------------------------------------------------------------------------
// Aggregation: warp per dst node, 2 edges per step.
// kv: ONE 256-bit evict_last load per lane per edge (k 4x half2 | v 4x half2).
// ---------------------------------------------------------------------------
__device__ __forceinline__ void edge_compute(
    int ok, const ulonglong4& kv4, float4 ea4,
    const __half2* qh, float4 g4, float* acc, float& den)
{
    const __half2* kvp = (const __half2*)&kv4;   // [0..3]=k, [4..7]=v
    __half2 p = __hmul2(qh[0], kvp[0]);
    p = __hfma2(qh[1], kvp[1], p);
    p = __hfma2(qh[2], kvp[2], p);
    p = __hfma2(qh[3], kvp[3], p);
    float2 pf = __half22float2(p);
    float dot = pf.x + pf.y
              + g4.x * ea4.x + g4.y * ea4.y + g4.z * ea4.z + g4.w * ea4.w;
    dot += __shfl_xor_sync(0xffffffffu, dot, 1);
    dot += __shfl_xor_sync(0xffffffffu, dot, 2);
    float ex = ok ? __expf(dot * 0.17677669529663687f) : 0.f;  // 1/sqrt(32)
    den += ex;
    float2 v01 = __half22float2(kvp[4]);
    float2 v23 = __half22float2(kvp[5]);
    float2 v45 = __half22float2(kvp[6]);
    float2 v67 = __half22float2(kvp[7]);
    acc[0] += ex * v01.x; acc[1] += ex * v01.y;
    acc[2] += ex * v23.x; acc[3] += ex * v23.y;
    acc[4] += ex * v45.x; acc[5] += ex * v45.y;
    acc[6] += ex * v67.x; acc[7] += ex * v67.y;
}

__global__ void __launch_bounds__(256)
agg_kernel(const float* __restrict__ edge_attr,
           const float* __restrict__ Wbeta,
           float* __restrict__ out, int n)
{
    int warp = (blockIdx.x * blockDim.x + threadIdx.x) >> 5;
    int lane = threadIdx.x & 31;
    if (warp >= n) return;
    int node = warp;
    int l16 = lane & 15;
    int half = lane >> 4;
    int hd = l16 >> 2;

    unsigned long long pol_strm = policy_stream();

    uint4 qv = *(const uint4*)&d_qh[node * 128 + l16 * 8];
    __half2 qh[4];
    qh[0] = *(__half2*)&qv.x; qh[1] = *(__half2*)&qv.y;
    qh[2] = *(__half2*)&qv.z; qh[3] = *(__half2*)&qv.w;
    uint2 gv = *(const uint2*)&d_gh[node * 64 + hd * 16 + (l16 & 3) * 4];
    float2 ga = __half22float2(*(__half2*)&gv.x);
    float2 gb = __half22float2(*(__half2*)&gv.y);
    float4 g4 = make_float4(ga.x, ga.y, gb.x, gb.y);

    int deg = d_count[node];
    if (deg > BCAP) deg = BCAP;

    float acc[8];
#pragma unroll
    for (int i = 0; i < 8; ++i) acc[i] = 0.f;
    float den = 0.f;

    for (int j0 = 0; j0 < deg; j0 += 32) {
        int jb = min(32, deg - j0);
        int e_l = 0, s_l = 0;
        if (lane < jb) {
            int2 es = ldg_hint2i(&d_bucket[node * BCAP + j0 + lane], pol_strm);
            e_l = es.x; s_l = es.y;
        }
        int steps = (jb + 1) >> 1;
        int j = 0;
        for (; j + 2 <= steps; j += 2) {
            int i0 = 2 * j + half, i1 = 2 * j + 2 + half;
            int ok0 = i0 < jb, ok1 = i1 < jb;
            int e0 = __shfl_sync(0xffffffffu, e_l, i0);
            int s0 = __shfl_sync(0xffffffffu, s_l, i0);
            int e1 = __shfl_sync(0xffffffffu, e_l, i1 & 31);
            int s1 = __shfl_sync(0xffffffffu, s_l, i1 & 31);
            ulonglong4 kv0 = ldg256_keep(&d_kvh[s0 * 256 + l16 * 16]);
            ulonglong4 kv1 = ldg256_keep(&d_kvh[s1 * 256 + l16 * 16]);
            float4 ea0 = ldg_hint4f(&edge_attr[e0 * 16 + (l16 & 3) * 4], pol_strm);
            float4 ea1 = ldg_hint4f(&edge_attr[e1 * 16 + (l16 & 3) * 4], pol_strm);
            edge_compute(ok0, kv0, ea0, qh, g4, acc, den);
            edge_compute(ok1, kv1, ea1, qh, g4, acc, den);
        }
        for (; j < steps; ++j) {
            int i0 = 2 * j + half;
            int ok0 = i0 < jb;
            int e0 = __shfl_sync(0xffffffffu, e_l, i0 & 31);
            int s0 = __shfl_sync(0xffffffffu, s_l, i0 & 31);
            ulonglong4 kv0 = ldg256_keep(&d_kvh[s0 * 256 + l16 * 16]);
            float4 ea0 = ldg_hint4f(&edge_attr[e0 * 16 + (l16 & 3) * 4], pol_strm);
            edge_compute(ok0, kv0, ea0, qh, g4, acc, den);
        }
    }

#pragma unroll
    for (int i = 0; i < 8; ++i)
        acc[i] += __shfl_xor_sync(0xffffffffu, acc[i], 16);
    den += __shfl_xor_sync(0xffffffffu, den, 16);

    float inv = 1.f / (den + 1e-16f);
    float o[8];
#pragma unroll
    for (int i = 0; i < 8; ++i) o[i] = acc[i] * inv;

    int cb = l16 * 8;
    // skip fp16: 8 halfs = 16B
    uint4 xv4 = *(const uint4*)&d_sh[node * 128 + cb];
    float2 x01 = __half22float2(*(__half2*)&xv4.x);
    float2 x23 = __half22float2(*(__half2*)&xv4.y);
    float2 x45 = __half22float2(*(__half2*)&xv4.z);
    float2 x67 = __half22float2(*(__half2*)&xv4.w);
    float xs[8] = {x01.x, x01.y, x23.x, x23.y, x45.x, x45.y, x67.x, x67.y};

    float4 w0A = *(const float4*)&Wbeta[cb];
    float4 w0B = *(const float4*)&Wbeta[cb + 4];
    float4 w1A = *(const float4*)&Wbeta[128 + cb];
    float4 w1B = *(const float4*)&Wbeta[128 + cb + 4];
    float4 w2A = *(const float4*)&Wbeta[256 + cb];
    float4 w2B = *(const float4*)&Wbeta[256 + cb + 4];
    float w0[8] = {w0A.x, w0A.y, w0A.z, w0A.w, w0B.x, w0B.y, w0B.z, w0B.w};
    float w1[8] = {w1A.x, w1A.y, w1A.z, w1A.w, w1B.x, w1B.y, w1B.z, w1B.w};
    float w2[8] = {w2A.x, w2A.y, w2A.z, w2A.w, w2B.x, w2B.y, w2B.z, w2B.w};
    float s = 0.f;
#pragma unroll
    for (int i = 0; i < 8; ++i)
        s += o[i] * (w0[i] + w2[i]) + xs[i] * (w1[i] - w2[i]);
    s += __shfl_xor_sync(0xffffffffu, s, 1);
    s += __shfl_xor_sync(0xffffffffu, s, 2);
    s += __shfl_xor_sync(0xffffffffu, s, 4);
    s += __shfl_xor_sync(0xffffffffu, s, 8);
    float beta = 1.f / (1.f + __expf(-s));

    if (half == 0) {
        float r[8];
#pragma unroll
        for (int i = 0; i < 8; ++i)
            r[i] = beta * xs[i] + (1.f - beta) * o[i];
        stg_stream4f(&out[node * 128 + cb], make_float4(r[0], r[1], r[2], r[3]));
        stg_stream4f(&out[node * 128 + cb + 4], make_float4(r[4], r[5], r[6], r[7]));
    }
}

// ---------------------------------------------------------------------------
extern "C" void kernel_launch(void* const* d_in, const int* in_sizes, int n_in,
                              void* d_out, int out_size)
{
    const float* x         = (const float*)d_in[0];
    const float* edge_attr = (const float*)d_in[1];
    const int*   edge_idx  = (const int*)  d_in[2];
    const float* Wq = (const float*)d_in[3];
    const float* bq = (const float*)d_in[4];
    const float* Wk = (const float*)d_in[5];
    const float* bk = (const float*)d_in[6];
    const float* Wv = (const float*)d_in[7];
    const float* bv = (const float*)d_in[8];
    const float* We = (const float*)d_in[9];
    const float* Ws = (const float*)d_in[10];
    const float* bs = (const float*)d_in[11];
    const float* Wbeta = (const float*)d_in[12];
    float* out = (float*)d_out;

    int n = in_sizes[0] / 128;
    int e = in_sizes[1] / 16;
    const int* row  = edge_idx;      // destination nodes
    const int* colv = edge_idx + e;  // source nodes

    cudaFuncSetAttribute(proj_mma, cudaFuncAttributeMaxDynamicSharedMemorySize,
                         PROJ_SMEM);

    prep_kernel<<<288 + (MAXN + 255) / 256, 256>>>(Wq, Wk, Wv, Ws, We, bq);
    fill_buckets<<<(e + 255) / 256, 256>>>(row, colv, e);
    proj_mma<<<(n + 255) / 256, 512, PROJ_SMEM>>>(x, bq, bk, bv, bs, n);
    agg_kernel<<<((long long)n * 32 + 255) / 256, 256>>>(edge_attr, Wbeta, out, n);
}

// round 16
// speedup vs baseline: 1.1082x; 1.1082x over previous
#include <cuda_runtime.h>
#include <cuda_bf16.h>
#include <cuda_fp16.h>
#include <cstdint>

// ---------------------------------------------------------------------------
// TransformerConv: N=100000 nodes, E=1600000 edges, IN=128, H=4, C=32, ED=16
//
// sm_103 base target (NO tcgen05 — harness PTX is .target sm_103):
//   1) prep_kernel : W{q,k,v,skip}->fp16 [512x128] + Wg fold + zero d_count
//   2) fill_buckets: bucket {edge,src} pairs by destination node
//   3) proj_mma    : fp16 mma.sync, M=256/512thr, cp.async double-buffered B
//   4) agg_kernel  : warp-per-dst-node, 2 edges/step; kv split k|v, two
//                    independent 16B cache_hint(evict_last) loads per edge
//                    (R15's fused 256-bit load REGRESSED: less MLP);
//                    skip+g in fp16 (-114MB DRAM)
// ---------------------------------------------------------------------------

#define MAXN 100096
#define BCAP 96   // per-node bucket capacity (Poisson(16) max ~36; 96 is safe)

__device__ __half d_sh[MAXN * 128];    // skip fp16
__device__ __half d_gh[MAXN * 64];     // g fp16
__device__ __half d_qh[MAXN * 128];    // q fp16, ch-major
__device__ __half d_kvh[MAXN * 256];   // per node: k[128] fp16 | v[128] fp16
__device__ int    d_count[MAXN];
__device__ int2   d_bucket[MAXN * BCAP];  // {edge id, src node}
__device__ __half d_B[576 * 128];      // W^T fp16, n-major rows, k cols (+Wg)
__device__ float  d_bg[64];            // bias for folded g projection

// ============================ helpers ======================================
__device__ __forceinline__ uint32_t smem_u32(const void* p) {
    uint32_t a;
    asm("{ .reg .u64 t; cvta.to.shared.u64 t, %1; cvt.u32.u64 %0, t; }"
        : "=r"(a) : "l"(p));
    return a;
}
__device__ __forceinline__ void ldm_x4(uint32_t& r0, uint32_t& r1,
                                       uint32_t& r2, uint32_t& r3, uint32_t addr) {
    asm volatile("ldmatrix.sync.aligned.m8n8.x4.shared.b16 {%0,%1,%2,%3}, [%4];"
                 : "=r"(r0), "=r"(r1), "=r"(r2), "=r"(r3) : "r"(addr));
}
__device__ __forceinline__ void mma_f16(float* c, const uint32_t* a,
                                        uint32_t b0, uint32_t b1) {
    asm volatile(
        "mma.sync.aligned.m16n8k16.row.col.f32.f16.f16.f32 "
        "{%0,%1,%2,%3}, {%4,%5,%6,%7}, {%8,%9}, {%0,%1,%2,%3};"
        : "+f"(c[0]), "+f"(c[1]), "+f"(c[2]), "+f"(c[3])
        : "r"(a[0]), "r"(a[1]), "r"(a[2]), "r"(a[3]), "r"(b0), "r"(b1));
}
__device__ __forceinline__ void cp_async16(uint32_t saddr, const void* gptr) {
    asm volatile("cp.async.ca.shared.global [%0], [%1], 16;"
                 :: "r"(saddr), "l"(gptr));
}
__device__ __forceinline__ void cp_commit() {
    asm volatile("cp.async.commit_group;");
}
__device__ __forceinline__ void cp_wait0() {
    asm volatile("cp.async.wait_group 0;");
}
// L2 cache policies (createpolicy form — direct 16B ld modifier rejected)
__device__ __forceinline__ unsigned long long policy_keep() {
    unsigned long long p;
    asm("createpolicy.fractional.L2::evict_last.b64 %0, 1.0;" : "=l"(p));
    return p;
}
__device__ __forceinline__ unsigned long long policy_stream() {
    unsigned long long p;
    asm("createpolicy.fractional.L2::evict_first.b64 %0, 1.0;" : "=l"(p));
    return p;
}
__device__ __forceinline__ uint4 ldg_hint4u(const void* p, unsigned long long pol) {
    uint4 r;
    asm volatile("ld.global.nc.L2::cache_hint.v4.u32 {%0,%1,%2,%3}, [%4], %5;"
                 : "=r"(r.x), "=r"(r.y), "=r"(r.z), "=r"(r.w)
                 : "l"(p), "l"(pol));
    return r;
}
__device__ __forceinline__ float4 ldg_hint4f(const void* p, unsigned long long pol) {
    float4 r;
    asm volatile("ld.global.nc.L2::cache_hint.v4.f32 {%0,%1,%2,%3}, [%4], %5;"
                 : "=f"(r.x), "=f"(r.y), "=f"(r.z), "=f"(r.w)
                 : "l"(p), "l"(pol));
    return r;
}
__device__ __forceinline__ int2 ldg_hint2i(const void* p, unsigned long long pol) {
    int2 r;
    asm volatile("ld.global.nc.L2::cache_hint.v2.u32 {%0,%1}, [%2], %3;"
                 : "=r"(r.x), "=r"(r.y) : "l"(p), "l"(pol));
    return r;
}
__device__ __forceinline__ void stg_stream4f(void* p, float4 v) {
    asm volatile("st.global.cs.v4.f32 [%0], {%1,%2,%3,%4};"
                 :: "l"(p), "f"(v.x), "f"(v.y), "f"(v.z), "f"(v.w));
}

// ---------------------------------------------------------------------------
// prep: blocks [0,256): W pack; [256,288): Wg fold; [288,...): zero d_count
// ---------------------------------------------------------------------------
__global__ void __launch_bounds__(256)
prep_kernel(const float* __restrict__ Wq, const float* __restrict__ Wk,
            const float* __restrict__ Wv, const float* __restrict__ Ws,
            const float* __restrict__ We, const float* __restrict__ bq)
{
    int b = blockIdx.x, tid = threadIdx.x;
    if (b < 256) {
        int i = b * 256 + tid;               // 65536 elements
        int k = i >> 9, nn = i & 511;
        int w = nn >> 7, c = nn & 127;
        const float* W = (w == 0) ? Wq : (w == 1) ? Wk : (w == 2) ? Wv : Ws;
        d_B[nn * 128 + k] = __float2half_rn(W[k * 128 + c]);
    } else if (b < 288) {
        int t = (b - 256) * 256 + tid;       // 8192: (i, o)
        int i = t >> 6, o = t & 63;
        int h = o >> 4, d = o & 15;
        float s = 0.f;
#pragma unroll
        for (int c = 0; c < 32; ++c)
            s += Wq[i * 128 + h * 32 + c] * We[d * 128 + h * 32 + c];
        d_B[(512 + o) * 128 + i] = __float2half_rn(s);
        if (i == 0) {
            float sb = 0.f;
#pragma unroll
            for (int c = 0; c < 32; ++c)
                sb += bq[h * 32 + c] * We[d * 128 + h * 32 + c];
            d_bg[o] = sb;
        }
    } else {
        int i = (b - 288) * 256 + tid;
        if (i < MAXN) d_count[i] = 0;
    }
}

// ---------------------------------------------------------------------------
// Edge bucketing: store {edge, src} pairs
// ---------------------------------------------------------------------------
__global__ void __launch_bounds__(256)
fill_buckets(const int* __restrict__ row, const int* __restrict__ colv, int e)
{
    int i = blockIdx.x * blockDim.x + threadIdx.x;
    if (i >= e) return;
    int dst = row[i];
    int src = colv[i];
    int pos = atomicAdd(&d_count[dst], 1);
    if (pos < BCAP) d_bucket[dst * BCAP + pos] = make_int2(i, src);
}

// ---------------------------------------------------------------------------
// Projection: M=256 tile / 512 threads; B double-buffered via cp.async.
// ---------------------------------------------------------------------------
#define ASTR 136
#define PROJ_SMEM ((256 + 256) * ASTR * 2)

template <int NF>
__device__ __forceinline__ void mma_chunk(uint32_t uA, uint32_t uB,
                                          float (*acc)[4], int wid, int lane)
{
    uint32_t a_row = (uint32_t)(wid * 16 + (lane & 15));
    uint32_t a_koff = (uint32_t)((lane >> 4) * 8);
    uint32_t b_sub = (uint32_t)((lane >> 4) & 1);
    uint32_t b_kh  = (uint32_t)((lane >> 3) & 1);
    uint32_t b_rin = (uint32_t)(lane & 7);
#pragma unroll
    for (int ks = 0; ks < 8; ++ks) {
        uint32_t a[4];
        ldm_x4(a[0], a[1], a[2], a[3],
               uA + (a_row * ASTR + ks * 16 + a_koff) * 2);
#pragma unroll
        for (int p = 0; p < NF / 2; ++p) {
            uint32_t brow = (2 * p + b_sub) * 8 + b_rin;
            uint32_t b0, b1, b2, b3;
            ldm_x4(b0, b1, b2, b3,
                   uB + (brow * ASTR + ks * 16 + b_kh * 8) * 2);
            mma_f16(acc[2 * p], a, b0, b1);
            mma_f16(acc[2 * p + 1], a, b2, b3);
        }
    }
}

__device__ __forceinline__ void stage_B_async(ushort* sB, int nc, int NF, int tid)
{
    uint32_t ub = smem_u32(sB);
    for (int i = tid; i < NF * 8 * 16; i += 512) {
        int r = i >> 4, c8 = i & 15;
        cp_async16(ub + (uint32_t)(r * ASTR + c8 * 8) * 2,
                   &d_B[(nc * 128 + r) * 128 + c8 * 8]);
    }
    cp_commit();
}

__global__ void __launch_bounds__(512, 1)
proj_mma(const float* __restrict__ x,
         const float* __restrict__ bq, const float* __restrict__ bk,
         const float* __restrict__ bv, const float* __restrict__ bs,
         int n)
{
    extern __shared__ __align__(16) char smem[];
    ushort* sA  = (ushort*)smem;                // [256][ASTR]
    ushort* sB0 = sA + 256 * ASTR;              // [128][ASTR]
    ushort* sB1 = sB0 + 128 * ASTR;             // [128][ASTR]

    int tid = threadIdx.x, lane = tid & 31, wid = tid >> 5;
    int row0 = blockIdx.x * 256;

    stage_B_async(sB0, 0, 16, tid);

    for (int i = tid; i < 256 * 32; i += 512) {
        int r = i >> 5, c4 = i & 31;
        int node = row0 + r;
        float4 xv = (node < n) ? *(const float4*)&x[node * 128 + c4 * 4]
                               : make_float4(0.f, 0.f, 0.f, 0.f);
        __half2 h01 = __floats2half2_rn(xv.x, xv.y);
        __half2 h23 = __floats2half2_rn(xv.z, xv.w);
        *(uint2*)&sA[r * ASTR + c4 * 4] =
            make_uint2(*(uint32_t*)&h01, *(uint32_t*)&h23);
    }

    uint32_t uA = smem_u32(sA);
    ushort* sBcur = sB0;
    ushort* sBnxt = sB1;
    ushort* kvs = (ushort*)d_kvh;

    for (int nc = 0; nc < 5; ++nc) {
        cp_wait0();
        __syncthreads();
        if (nc < 4)
            stage_B_async(sBnxt, nc + 1, (nc + 1 == 4) ? 8 : 16, tid);

        float acc[16][4];
#pragma unroll
        for (int f = 0; f < 16; ++f)
#pragma unroll
            for (int j = 0; j < 4; ++j) acc[f][j] = 0.f;

        uint32_t uB = smem_u32(sBcur);
        if (nc == 4) mma_chunk<8>(uA, uB, acc, wid, lane);
        else         mma_chunk<16>(uA, uB, acc, wid, lane);

        int r_base = row0 + wid * 16 + (lane >> 2);
        if (nc == 4) {
#pragma unroll
            for (int nf = 0; nf < 8; ++nf) {
                int cn = nf * 8 + (lane & 3) * 2;
                float b0 = d_bg[cn], b1 = d_bg[cn + 1];
#pragma unroll
                for (int half = 0; half < 2; ++half) {
                    int node = r_base + half * 8;
                    if (node >= n) continue;
                    __half2 hh = __floats2half2_rn(acc[nf][half * 2] + b0,
                                                   acc[nf][half * 2 + 1] + b1);
                    *(__half2*)&d_gh[node * 64 + cn] = hh;
                }
            }
        } else {
            const float* bias = (nc == 0) ? bq : (nc == 1) ? bk : (nc == 2) ? bv : bs;
#pragma unroll
            for (int nf = 0; nf < 16; ++nf) {
                int cn = nf * 8 + (lane & 3) * 2;
                float b0 = __ldg(&bias[cn]), b1 = __ldg(&bias[cn + 1]);
#pragma unroll
                for (int half = 0; half < 2; ++half) {
                    int node = r_base + half * 8;
                    if (node >= n) continue;
                    float v0 = acc[nf][half * 2 + 0] + b0;
                    float v1 = acc[nf][half * 2 + 1] + b1;
                    __half2 hh = __floats2half2_rn(v0, v1);
                    if (nc == 3) {
                        *(__half2*)&d_sh[node * 128 + cn] = hh;
                    } else if (nc == 0) {
                        *(__half2*)&d_qh[node * 128 + cn] = hh;
                    } else {
                        // split layout: k at +0..127, v at +128..255
                        uint32_t idx = (uint32_t)node * 256 + cn
                                     + (nc == 2 ? 128 : 0);
                        *(uint32_t*)&kvs[idx] = *(uint32_t*)&hh;
                    }
                }
            }
        }
        ushort* t = sBcur; sBcur = sBnxt; sBnxt = t;
        __syncthreads();
    }
}

// ---------------------------------------------------------------------------
// Aggregation: warp per dst node, 2 edges per step; two independent 16B
// kv loads per edge per lane (max MLP), L2 policies via createpolicy.
// ---------------------------------------------------------------------------
__device__ __forceinline__ void edge_compute(
    int ok, uint4 kvec, uint4 vvec, float4 ea4,
    const __half2* qh, float4 g4, float* acc, float& den)
{
    __half2 p = __hmul2(qh[0], *(__half2*)&kvec.x);
    p = __hfma2(qh[1], *(((__half2*)&kvec.x) + 1), p);
    p = __hfma2(qh[2], *(((__half2*)&kvec.x) + 2), p);
    p = __hfma2(qh[3], *(((__half2*)&kvec.x) + 3), p);
    float2 pf = __half22float2(p);
    float dot = pf.x + pf.y
              + g4.x * ea4.x + g4.y * ea4.y + g4.z * ea4.z + g4.w * ea4.w;
    dot += __shfl_xor_sync(0xffffffffu, dot, 1);
    dot += __shfl_xor_sync(0xffffffffu, dot, 2);
    float ex = ok ? __expf(dot * 0.17677669529663687f) : 0.f;  // 1/sqrt(32)
    den += ex;
    float2 v01 = __half22float2(*(__half2*)&vvec.x);
    float2 v23 = __half22float2(*(((__half2*)&vvec.x) + 1));
    float2 v45 = __half22float2(*(((__half2*)&vvec.x) + 2));
    float2 v67 = __half22float2(*(((__half2*)&vvec.x) + 3));
    acc[0] += ex * v01.x; acc[1] += ex * v01.y;
    acc[2] += ex * v23.x; acc[3] += ex * v23.y;
    acc[4] += ex * v45.x; acc[5] += ex * v45.y;
    acc[6] += ex * v67.x; acc[7] += ex * v67.y;
}

__global__ void __launch_bounds__(256)
agg_kernel(const float* __restrict__ edge_attr,
           const float* __restrict__ Wbeta,
           float* __restrict__ out, int n)
{
    int warp = (blockIdx.x * blockDim.x + threadIdx.x) >> 5;
    int lane = threadIdx.x & 31;
    if (warp >= n) return;
    int node = warp;
    int l16 = lane & 15;
    int half = lane >> 4;
    int hd = l16 >> 2;

    unsigned long long pol_keep = policy_keep();
    unsigned long long pol_strm = policy_stream();

    uint4 qv = *(const uint4*)&d_qh[node * 128 + l16 * 8];
    __half2 qh[4];
    qh[0] = *(__half2*)&qv.x; qh[1] = *(__half2*)&qv.y;
    qh[2] = *(__half2*)&qv.z; qh[3] = *(__half2*)&qv.w;
    uint2 gv = *(const uint2*)&d_gh[node * 64 + hd * 16 + (l16 & 3) * 4];
    float2 ga = __half22float2(*(__half2*)&gv.x);
    float2 gb = __half22float2(*(__half2*)&gv.y);
    float4 g4 = make_float4(ga.x, ga.y, gb.x, gb.y);

    int deg = d_count[node];
    if (deg > BCAP) deg = BCAP;

    float acc[8];
#pragma unroll
    for (int i = 0; i < 8; ++i) acc[i] = 0.f;
    float den = 0.f;

    for (int j0 = 0; j0 < deg; j0 += 32) {
        int jb = min(32, deg - j0);
        int e_l = 0, s_l = 0;
        if (lane < jb) {
            int2 es = ldg_hint2i(&d_bucket[node * BCAP + j0 + lane], pol_strm);
            e_l = es.x; s_l = es.y;
        }
        int steps = (jb + 1) >> 1;
        int j = 0;
        for (; j + 2 <= steps; j += 2) {
            int i0 = 2 * j + half, i1 = 2 * j + 2 + half;
            int ok0 = i0 < jb, ok1 = i1 < jb;
            int e0 = __shfl_sync(0xffffffffu, e_l, i0);
            int s0 = __shfl_sync(0xffffffffu, s_l, i0);
            int e1 = __shfl_sync(0xffffffffu, e_l, i1 & 31);
            int s1 = __shfl_sync(0xffffffffu, s_l, i1 & 31);
            const __half* kb0 = &d_kvh[s0 * 256];
            const __half* kb1 = &d_kvh[s1 * 256];
            uint4 k0 = ldg_hint4u(&kb0[l16 * 8], pol_keep);
            uint4 v0 = ldg_hint4u(&kb0[128 + l16 * 8], pol_keep);
            uint4 k1 = ldg_hint4u(&kb1[l16 * 8], pol_keep);
            uint4 v1 = ldg_hint4u(&kb1[128 + l16 * 8], pol_keep);
            float4 ea0 = ldg_hint4f(&edge_attr[e0 * 16 + (l16 & 3) * 4], pol_strm);
            float4 ea1 = ldg_hint4f(&edge_attr[e1 * 16 + (l16 & 3) * 4], pol_strm);
            edge_compute(ok0, k0, v0, ea0, qh, g4, acc, den);
            edge_compute(ok1, k1, v1, ea1, qh, g4, acc, den);
        }
        for (; j < steps; ++j) {
            int i0 = 2 * j + half;
            int ok0 = i0 < jb;
            int e0 = __shfl_sync(0xffffffffu, e_l, i0 & 31);
            int s0 = __shfl_sync(0xffffffffu, s_l, i0 & 31);
            const __half* kb0 = &d_kvh[s0 * 256];
            uint4 k0 = ldg_hint4u(&kb0[l16 * 8], pol_keep);
            uint4 v0 = ldg_hint4u(&kb0[128 + l16 * 8], pol_keep);
            float4 ea0 = ldg_hint4f(&edge_attr[e0 * 16 + (l16 & 3) * 4], pol_strm);
            edge_compute(ok0, k0, v0, ea0, qh, g4, acc, den);
        }
    }

#pragma unroll
    for (int i = 0; i < 8; ++i)
        acc[i] += __shfl_xor_sync(0xffffffffu, acc[i], 16);
    den += __shfl_xor_sync(0xffffffffu, den, 16);

    float inv = 1.f / (den + 1e-16f);
    float o[8];
#pragma unroll
    for (int i = 0; i < 8; ++i) o[i] = acc[i] * inv;

    int cb = l16 * 8;
    // skip fp16: 8 halfs = 16B
    uint4 xv4 = *(const uint4*)&d_sh[node * 128 + cb];
    float2 x01 = __half22float2(*(__half2*)&xv4.x);
    float2 x23 = __half22float2(*(__half2*)&xv4.y);
    float2 x45 = __half22float2(*(__half2*)&xv4.z);
    float2 x67 = __half22float2(*(__half2*)&xv4.w);
    float xs[8] = {x01.x, x01.y, x23.x, x23.y, x45.x, x45.y, x67.x, x67.y};

    float4 w0A = *(const float4*)&Wbeta[cb];
    float4 w0B = *(const float4*)&Wbeta[cb + 4];
    float4 w1A = *(const float4*)&Wbeta[128 + cb];
    float4 w1B = *(const float4*)&Wbeta[128 + cb + 4];
    float4 w2A = *(const float4*)&Wbeta[256 + cb];
    float4 w2B = *(const float4*)&Wbeta[256 + cb + 4];
    float w0[8] = {w0A.x, w0A.y, w0A.z, w0A.w, w0B.x, w0B.y, w0B.z, w0B.w};
    float w1[8] = {w1A.x, w1A.y, w1A.z, w1A.w, w1B.x, w1B.y, w1B.z, w1B.w};
    float w2[8] = {w2A.x, w2A.y, w2A.z, w2A.w, w2B.x, w2B.y, w2B.z, w2B.w};
    float s = 0.f;
#pragma unroll
    for (int i = 0; i < 8; ++i)
        s += o[i] * (w0[i] + w2[i]) + xs[i] * (w1[i] - w2[i]);
    s += __shfl_xor_sync(0xffffffffu, s, 1);
    s += __shfl_xor_sync(0xffffffffu, s, 2);
    s += __shfl_xor_sync(0xffffffffu, s, 4);
    s += __shfl_xor_sync(0xffffffffu, s, 8);
    float beta = 1.f / (1.f + __expf(-s));

    if (half == 0) {
        float r[8];
#pragma unroll
        for (int i = 0; i < 8; ++i)
            r[i] = beta * xs[i] + (1.f - beta) * o[i];
        stg_stream4f(&out[node * 128 + cb], make_float4(r[0], r[1], r[2], r[3]));
        stg_stream4f(&out[node * 128 + cb + 4], make_float4(r[4], r[5], r[6], r[7]));
    }
}

// ---------------------------------------------------------------------------
extern "C" void kernel_launch(void* const* d_in, const int* in_sizes, int n_in,
                              void* d_out, int out_size)
{
    const float* x         = (const float*)d_in[0];
    const float* edge_attr = (const float*)d_in[1];
    const int*   edge_idx  = (const int*)  d_in[2];
    const float* Wq = (const float*)d_in[3];
    const float* bq = (const float*)d_in[4];
    const float* Wk = (const float*)d_in[5];
    const float* bk = (const float*)d_in[6];
    const float* Wv = (const float*)d_in[7];
    const float* bv = (const float*)d_in[8];
    const float* We = (const float*)d_in[9];
    const float* Ws = (const float*)d_in[10];
    const float* bs = (const float*)d_in[11];
    const float* Wbeta = (const float*)d_in[12];
    float* out = (float*)d_out;

    int n = in_sizes[0] / 128;
    int e = in_sizes[1] / 16;
    const int* row  = edge_idx;      // destination nodes
    const int* colv = edge_idx + e;  // source nodes

    cudaFuncSetAttribute(proj_mma, cudaFuncAttributeMaxDynamicSharedMemorySize,
                         PROJ_SMEM);

    prep_kernel<<<288 + (MAXN + 255) / 256, 256>>>(Wq, Wk, Wv, Ws, We, bq);
    fill_buckets<<<(e + 255) / 256, 256>>>(row, colv, e);
    proj_mma<<<(n + 255) / 256, 512, PROJ_SMEM>>>(x, bq, bk, bv, bs, n);
    agg_kernel<<<((long long)n * 32 + 255) / 256, 256>>>(edge_attr, Wbeta, out, n);
}

// round 17
// speedup vs baseline: 1.1408x; 1.0295x over previous
#include <cuda_runtime.h>
#include <cuda_bf16.h>
#include <cuda_fp16.h>
#include <cstdint>

// ---------------------------------------------------------------------------
// TransformerConv: N=100000 nodes, E=1600000 edges, IN=128, H=4, C=32, ED=16
//
// sm_103 base target (NO tcgen05 — harness PTX is .target sm_103):
//   1) prep_kernel : W pack fp16 + Wg fold + Wbeta combine + zero d_count
//   2) {fill_buckets ∥ proj_mma}  — independent; forked onto a second stream
//      under graph capture so fill's 25us hides beneath proj
//   3) agg_kernel  : warp-per-dst-node, 2 edges/step, split k|v 16B gathers
//                    with L2 evict_last policy; fp16 q/k/v/skip/g
// ---------------------------------------------------------------------------

#define MAXN 100096
#define BCAP 96   // per-node bucket capacity (Poisson(16) max ~36; 96 is safe)

__device__ __half d_sh[MAXN * 128];    // skip fp16
__device__ __half d_gh[MAXN * 64];     // g fp16
__device__ __half d_qh[MAXN * 128];    // q fp16, ch-major
__device__ __half d_kvh[MAXN * 256];   // per node: k[128] fp16 | v[128] fp16
__device__ int    d_count[MAXN];
__device__ int2   d_bucket[MAXN * BCAP];  // {edge id, src node}
__device__ __half d_B[576 * 128];      // W^T fp16, n-major rows, k cols (+Wg)
__device__ float  d_bg[64];            // bias for folded g projection
__device__ float  d_wc[256];           // [0:128)=Wb0+Wb2, [128:256)=Wb1-Wb2

// ============================ helpers ======================================
__device__ __forceinline__ uint32_t smem_u32(const void* p) {
    uint32_t a;
    asm("{ .reg .u64 t; cvta.to.shared.u64 t, %1; cvt.u32.u64 %0, t; }"
        : "=r"(a) : "l"(p));
    return a;
}
__device__ __forceinline__ void ldm_x4(uint32_t& r0, uint32_t& r1,
                                       uint32_t& r2, uint32_t& r3, uint32_t addr) {
    asm volatile("ldmatrix.sync.aligned.m8n8.x4.shared.b16 {%0,%1,%2,%3}, [%4];"
                 : "=r"(r0), "=r"(r1), "=r"(r2), "=r"(r3) : "r"(addr));
}
__device__ __forceinline__ void mma_f16(float* c, const uint32_t* a,
                                        uint32_t b0, uint32_t b1) {
    asm volatile(
        "mma.sync.aligned.m16n8k16.row.col.f32.f16.f16.f32 "
        "{%0,%1,%2,%3}, {%4,%5,%6,%7}, {%8,%9}, {%0,%1,%2,%3};"
        : "+f"(c[0]), "+f"(c[1]), "+f"(c[2]), "+f"(c[3])
        : "r"(a[0]), "r"(a[1]), "r"(a[2]), "r"(a[3]), "r"(b0), "r"(b1));
}
__device__ __forceinline__ void cp_async16(uint32_t saddr, const void* gptr) {
    asm volatile("cp.async.ca.shared.global [%0], [%1], 16;"
                 :: "r"(saddr), "l"(gptr));
}
__device__ __forceinline__ void cp_commit() {
    asm volatile("cp.async.commit_group;");
}
__device__ __forceinline__ void cp_wait0() {
    asm volatile("cp.async.wait_group 0;");
}
// L2 cache policies (createpolicy form — direct 16B ld modifier rejected)
__device__ __forceinline__ unsigned long long policy_keep() {
    unsigned long long p;
    asm("createpolicy.fractional.L2::evict_last.b64 %0, 1.0;" : "=l"(p));
    return p;
}
__device__ __forceinline__ unsigned long long policy_stream() {
    unsigned long long p;
    asm("createpolicy.fractional.L2::evict_first.b64 %0, 1.0;" : "=l"(p));
    return p;
}
__device__ __forceinline__ uint4 ldg_hint4u(const void* p, unsigned long long pol) {
    uint4 r;
    asm volatile("ld.global.nc.L2::cache_hint.v4.u32 {%0,%1,%2,%3}, [%4], %5;"
                 : "=r"(r.x), "=r"(r.y), "=r"(r.z), "=r"(r.w)
                 : "l"(p), "l"(pol));
    return r;
}
__device__ __forceinline__ float4 ldg_hint4f(const void* p, unsigned long long pol) {
    float4 r;
    asm volatile("ld.global.nc.L2::cache_hint.v4.f32 {%0,%1,%2,%3}, [%4], %5;"
                 : "=f"(r.x), "=f"(r.y), "=f"(r.z), "=f"(r.w)
                 : "l"(p), "l"(pol));
    return r;
}
__device__ __forceinline__ int2 ldg_hint2i(const void* p, unsigned long long pol) {
    int2 r;
    asm volatile("ld.global.nc.L2::cache_hint.v2.u32 {%0,%1}, [%2], %3;"
                 : "=r"(r.x), "=r"(r.y) : "l"(p), "l"(pol));
    return r;
}
__device__ __forceinline__ void stg_stream4f(void* p, float4 v) {
    asm volatile("st.global.cs.v4.f32 [%0], {%1,%2,%3,%4};"
                 :: "l"(p), "f"(v.x), "f"(v.y), "f"(v.z), "f"(v.w));
}

// ---------------------------------------------------------------------------
// prep: b<256: W pack; b<288: Wg fold; b==288: Wbeta combine; b>288: zero
// ---------------------------------------------------------------------------
__global__ void __launch_bounds__(256)
prep_kernel(const float* __restrict__ Wq, const float* __restrict__ Wk,
            const float* __restrict__ Wv, const float* __restrict__ Ws,
            const float* __restrict__ We, const float* __restrict__ bq,
            const float* __restrict__ Wbeta)
{
    int b = blockIdx.x, tid = threadIdx.x;
    if (b < 256) {
        int i = b * 256 + tid;               // 65536 elements
        int k = i >> 9, nn = i & 511;
        int w = nn >> 7, c = nn & 127;
        const float* W = (w == 0) ? Wq : (w == 1) ? Wk : (w == 2) ? Wv : Ws;
        d_B[nn * 128 + k] = __float2half_rn(W[k * 128 + c]);
    } else if (b < 288) {
        int t = (b - 256) * 256 + tid;       // 8192: (i, o)
        int i = t >> 6, o = t & 63;
        int h = o >> 4, d = o & 15;
        float s = 0.f;
#pragma unroll
        for (int c = 0; c < 32; ++c)
            s += Wq[i * 128 + h * 32 + c] * We[d * 128 + h * 32 + c];
        d_B[(512 + o) * 128 + i] = __float2half_rn(s);
        if (i == 0) {
            float sb = 0.f;
#pragma unroll
            for (int c = 0; c < 32; ++c)
                sb += bq[h * 32 + c] * We[d * 128 + h * 32 + c];
            d_bg[o] = sb;
        }
    } else if (b == 288) {
        // Wbeta combine: wc0 = Wb0+Wb2 (t<128), wc1 = Wb1-Wb2 (t>=128)
        if (tid < 128)
            d_wc[tid] = Wbeta[tid] + Wbeta[256 + tid];
        else
            d_wc[tid] = Wbeta[tid] - Wbeta[128 + tid];  // Wbeta[128+c]-Wbeta[256+c]
    } else {
        int i = (b - 289) * 256 + tid;
        if (i < MAXN) d_count[i] = 0;
    }
}

// ---------------------------------------------------------------------------
// Edge bucketing: store {edge, src} pairs
// ---------------------------------------------------------------------------
__global__ void __launch_bounds__(256)
fill_buckets(const int* __restrict__ row, const int* __restrict__ colv, int e)
{
    int i = blockIdx.x * blockDim.x + threadIdx.x;
    if (i >= e) return;
    int dst = row[i];
    int src = colv[i];
    int pos = atomicAdd(&d_count[dst], 1);
    if (pos < BCAP) d_bucket[dst * BCAP + pos] = make_int2(i, src);
}

// ---------------------------------------------------------------------------
// Projection: M=256 tile / 512 threads; B double-buffered via cp.async.
// ---------------------------------------------------------------------------
#define ASTR 136
#define PROJ_SMEM ((256 + 256) * ASTR * 2)

template <int NF>
__device__ __forceinline__ void mma_chunk(uint32_t uA, uint32_t uB,
                                          float (*acc)[4], int wid, int lane)
{
    uint32_t a_row = (uint32_t)(wid * 16 + (lane & 15));
    uint32_t a_koff = (uint32_t)((lane >> 4) * 8);
    uint32_t b_sub = (uint32_t)((lane >> 4) & 1);
    uint32_t b_kh  = (uint32_t)((lane >> 3) & 1);
    uint32_t b_rin = (uint32_t)(lane & 7);
#pragma unroll
    for (int ks = 0; ks < 8; ++ks) {
        uint32_t a[4];
        ldm_x4(a[0], a[1], a[2], a[3],
               uA + (a_row * ASTR + ks * 16 + a_koff) * 2);
#pragma unroll
        for (int p = 0; p < NF / 2; ++p) {
            uint32_t brow = (2 * p + b_sub) * 8 + b_rin;
            uint32_t b0, b1, b2, b3;
            ldm_x4(b0, b1, b2, b3,
                   uB + (brow * ASTR + ks * 16 + b_kh * 8) * 2);
            mma_f16(acc[2 * p], a, b0, b1);
            mma_f16(acc[2 * p + 1], a, b2, b3);
        }
    }
}

__device__ __forceinline__ void stage_B_async(ushort* sB, int nc, int NF, int tid)
{
    uint32_t ub = smem_u32(sB);
    for (int i = tid; i < NF * 8 * 16; i += 512) {
        int r = i >> 4, c8 = i & 15;
        cp_async16(ub + (uint32_t)(r * ASTR + c8 * 8) * 2,
                   &d_B[(nc * 128 + r) * 128 + c8 * 8]);
    }
    cp_commit();
}

__global__ void __launch_bounds__(512, 1)
proj_mma(const float* __restrict__ x,
         const float* __restrict__ bq, const float* __restrict__ bk,
         const float* __restrict__ bv, const float* __restrict__ bs,
         int n)
{
    extern __shared__ __align__(16) char smem[];
    ushort* sA  = (ushort*)smem;                // [256][ASTR]
    ushort* sB0 = sA + 256 * ASTR;              // [128][ASTR]
    ushort* sB1 = sB0 + 128 * ASTR;             // [128][ASTR]

    int tid = threadIdx.x, lane = tid & 31, wid = tid >> 5;
    int row0 = blockIdx.x * 256;

    stage_B_async(sB0, 0, 16, tid);

    for (int i = tid; i < 256 * 32; i += 512) {
        int r = i >> 5, c4 = i & 31;
        int node = row0 + r;
        float4 xv = (node < n) ? *(const float4*)&x[node * 128 + c4 * 4]
                               : make_float4(0.f, 0.f, 0.f, 0.f);
        __half2 h01 = __floats2half2_rn(xv.x, xv.y);
        __half2 h23 = __floats2half2_rn(xv.z, xv.w);
        *(uint2*)&sA[r * ASTR + c4 * 4] =
            make_uint2(*(uint32_t*)&h01, *(uint32_t*)&h23);
    }

    uint32_t uA = smem_u32(sA);
    ushort* sBcur = sB0;
    ushort* sBnxt = sB1;
    ushort* kvs = (ushort*)d_kvh;

    for (int nc = 0; nc < 5; ++nc) {
        cp_wait0();
        __syncthreads();
        if (nc < 4)
            stage_B_async(sBnxt, nc + 1, (nc + 1 == 4) ? 8 : 16, tid);

        float acc[16][4];
#pragma unroll
        for (int f = 0; f < 16; ++f)
#pragma unroll
            for (int j = 0; j < 4; ++j) acc[f][j] = 0.f;

        uint32_t uB = smem_u32(sBcur);
        if (nc == 4) mma_chunk<8>(uA, uB, acc, wid, lane);
        else         mma_chunk<16>(uA, uB, acc, wid, lane);

        int r_base = row0 + wid * 16 + (lane >> 2);
        if (nc == 4) {
#pragma unroll
            for (int nf = 0; nf < 8; ++nf) {
                int cn = nf * 8 + (lane & 3) * 2;
                float b0 = d_bg[cn], b1 = d_bg[cn + 1];
#pragma unroll
                for (int half = 0; half < 2; ++half) {
                    int node = r_base + half * 8;
                    if (node >= n) continue;
                    __half2 hh = __floats2half2_rn(acc[nf][half * 2] + b0,
                                                   acc[nf][half * 2 + 1] + b1);
                    *(__half2*)&d_gh[node * 64 + cn] = hh;
                }
            }
        } else {
            const float* bias = (nc == 0) ? bq : (nc == 1) ? bk : (nc == 2) ? bv : bs;
#pragma unroll
            for (int nf = 0; nf < 16; ++nf) {
                int cn = nf * 8 + (lane & 3) * 2;
                float b0 = __ldg(&bias[cn]), b1 = __ldg(&bias[cn + 1]);
#pragma unroll
                for (int half = 0; half < 2; ++half) {
                    int node = r_base + half * 8;
                    if (node >= n) continue;
                    float v0 = acc[nf][half * 2 + 0] + b0;
                    float v1 = acc[nf][half * 2 + 1] + b1;
                    __half2 hh = __floats2half2_rn(v0, v1);
                    if (nc == 3) {
                        *(__half2*)&d_sh[node * 128 + cn] = hh;
                    } else if (nc == 0) {
                        *(__half2*)&d_qh[node * 128 + cn] = hh;
                    } else {
                        // split layout: k at +0..127, v at +128..255
                        uint32_t idx = (uint32_t)node * 256 + cn
                                     + (nc == 2 ? 128 : 0);
                        *(uint32_t*)&kvs[idx] = *(uint32_t*)&hh;
                    }
                }
            }
        }
        ushort* t = sBcur; sBcur = sBnxt; sBnxt = t;
        __syncthreads();
    }
}

// ---------------------------------------------------------------------------
// Aggregation: warp per dst node, 2 edges per step; two independent 16B
// kv loads per edge per lane (max MLP), L2 policies via createpolicy.
// ---------------------------------------------------------------------------
__device__ __forceinline__ void edge_compute(
    int ok, uint4 kvec, uint4 vvec, float4 ea4,
    const __half2* qh, float4 g4, float* acc, float& den)
{
    __half2 p = __hmul2(qh[0], *(__half2*)&kvec.x);
    p = __hfma2(qh[1], *(((__half2*)&kvec.x) + 1), p);
    p = __hfma2(qh[2], *(((__half2*)&kvec.x) + 2), p);
    p = __hfma2(qh[3], *(((__half2*)&kvec.x) + 3), p);
    float2 pf = __half22float2(p);
    float dot = pf.x + pf.y
              + g4.x * ea4.x + g4.y * ea4.y + g4.z * ea4.z + g4.w * ea4.w;
    dot += __shfl_xor_sync(0xffffffffu, dot, 1);
    dot += __shfl_xor_sync(0xffffffffu, dot, 2);
    float ex = ok ? __expf(dot * 0.17677669529663687f) : 0.f;  // 1/sqrt(32)
    den += ex;
    float2 v01 = __half22float2(*(__half2*)&vvec.x);
    float2 v23 = __half22float2(*(((__half2*)&vvec.x) + 1));
    float2 v45 = __half22float2(*(((__half2*)&vvec.x) + 2));
    float2 v67 = __half22float2(*(((__half2*)&vvec.x) + 3));
    acc[0] += ex * v01.x; acc[1] += ex * v01.y;
    acc[2] += ex * v23.x; acc[3] += ex * v23.y;
    acc[4] += ex * v45.x; acc[5] += ex * v45.y;
    acc[6] += ex * v67.x; acc[7] += ex * v67.y;
}

__global__ void __launch_bounds__(256)
agg_kernel(const float* __restrict__ edge_attr,
           float* __restrict__ out, int n)
{
    int warp = (blockIdx.x * blockDim.x + threadIdx.x) >> 5;
    int lane = threadIdx.x & 31;
    if (warp >= n) return;
    int node = warp;
    int l16 = lane & 15;
    int half = lane >> 4;
    int hd = l16 >> 2;

    unsigned long long pol_keep = policy_keep();
    unsigned long long pol_strm = policy_stream();

    uint4 qv = *(const uint4*)&d_qh[node * 128 + l16 * 8];
    __half2 qh[4];
    qh[0] = *(__half2*)&qv.x; qh[1] = *(__half2*)&qv.y;
    qh[2] = *(__half2*)&qv.z; qh[3] = *(__half2*)&qv.w;
    uint2 gv = *(const uint2*)&d_gh[node * 64 + hd * 16 + (l16 & 3) * 4];
    float2 ga = __half22float2(*(__half2*)&gv.x);
    float2 gb = __half22float2(*(__half2*)&gv.y);
    float4 g4 = make_float4(ga.x, ga.y, gb.x, gb.y);

    int deg = d_count[node];
    if (deg > BCAP) deg = BCAP;

    float acc[8];
#pragma unroll
    for (int i = 0; i < 8; ++i) acc[i] = 0.f;
    float den = 0.f;

    for (int j0 = 0; j0 < deg; j0 += 32) {
        int jb = min(32, deg - j0);
        int e_l = 0, s_l = 0;
        if (lane < jb) {
            int2 es = ldg_hint2i(&d_bucket[node * BCAP + j0 + lane], pol_strm);
            e_l = es.x; s_l = es.y;
        }
        int steps = (jb + 1) >> 1;
        int j = 0;
        for (; j + 2 <= steps; j += 2) {
            int i0 = 2 * j + half, i1 = 2 * j + 2 + half;
            int ok0 = i0 < jb, ok1 = i1 < jb;
            int e0 = __shfl_sync(0xffffffffu, e_l, i0);
            int s0 = __shfl_sync(0xffffffffu, s_l, i0);
            int e1 = __shfl_sync(0xffffffffu, e_l, i1 & 31);
            int s1 = __shfl_sync(0xffffffffu, s_l, i1 & 31);
            const __half* kb0 = &d_kvh[s0 * 256];
            const __half* kb1 = &d_kvh[s1 * 256];
            uint4 k0 = ldg_hint4u(&kb0[l16 * 8], pol_keep);
            uint4 v0 = ldg_hint4u(&kb0[128 + l16 * 8], pol_keep);
            uint4 k1 = ldg_hint4u(&kb1[l16 * 8], pol_keep);
            uint4 v1 = ldg_hint4u(&kb1[128 + l16 * 8], pol_keep);
            float4 ea0 = ldg_hint4f(&edge_attr[e0 * 16 + (l16 & 3) * 4], pol_strm);
            float4 ea1 = ldg_hint4f(&edge_attr[e1 * 16 + (l16 & 3) * 4], pol_strm);
            edge_compute(ok0, k0, v0, ea0, qh, g4, acc, den);
            edge_compute(ok1, k1, v1, ea1, qh, g4, acc, den);
        }
        for (; j < steps; ++j) {
            int i0 = 2 * j + half;
            int ok0 = i0 < jb;
            int e0 = __shfl_sync(0xffffffffu, e_l, i0 & 31);
            int s0 = __shfl_sync(0xffffffffu, s_l, i0 & 31);
            const __half* kb0 = &d_kvh[s0 * 256];
            uint4 k0 = ldg_hint4u(&kb0[l16 * 8], pol_keep);
            uint4 v0 = ldg_hint4u(&kb0[128 + l16 * 8], pol_keep);
            float4 ea0 = ldg_hint4f(&edge_attr[e0 * 16 + (l16 & 3) * 4], pol_strm);
            edge_compute(ok0, k0, v0, ea0, qh, g4, acc, den);
        }
    }

#pragma unroll
    for (int i = 0; i < 8; ++i)
        acc[i] += __shfl_xor_sync(0xffffffffu, acc[i], 16);
    den += __shfl_xor_sync(0xffffffffu, den, 16);

    float inv = 1.f / (den + 1e-16f);
    float o[8];
#pragma unroll
    for (int i = 0; i < 8; ++i) o[i] = acc[i] * inv;

    int cb = l16 * 8;
    // skip fp16: 8 halfs = 16B
    uint4 xv4 = *(const uint4*)&d_sh[node * 128 + cb];
    float2 x01 = __half22float2(*(__half2*)&xv4.x);
    float2 x23 = __half22float2(*(__half2*)&xv4.y);
    float2 x45 = __half22float2(*(__half2*)&xv4.z);
    float2 x67 = __half22float2(*(__half2*)&xv4.w);
    float xs[8] = {x01.x, x01.y, x23.x, x23.y, x45.x, x45.y, x67.x, x67.y};

    // precombined Wbeta: wc0 = Wb0+Wb2, wc1 = Wb1-Wb2
    float4 c0A = *(const float4*)&d_wc[cb];
    float4 c0B = *(const float4*)&d_wc[cb + 4];
    float4 c1A = *(const float4*)&d_wc[128 + cb];
    float4 c1B = *(const float4*)&d_wc[128 + cb + 4];
    float c0[8] = {c0A.x, c0A.y, c0A.z, c0A.w, c0B.x, c0B.y, c0B.z, c0B.w};
    float c1[8] = {c1A.x, c1A.y, c1A.z, c1A.w, c1B.x, c1B.y, c1B.z, c1B.w};
    float s = 0.f;
#pragma unroll
    for (int i = 0; i < 8; ++i)
        s += o[i] * c0[i] + xs[i] * c1[i];
    s += __shfl_xor_sync(0xffffffffu, s, 1);
    s += __shfl_xor_sync(0xffffffffu, s, 2);
    s += __shfl_xor_sync(0xffffffffu, s, 4);
    s += __shfl_xor_sync(0xffffffffu, s, 8);
    float beta = 1.f / (1.f + __expf(-s));

    if (half == 0) {
        float r[8];
#pragma unroll
        for (int i = 0; i < 8; ++i)
            r[i] = beta * xs[i] + (1.f - beta) * o[i];
        stg_stream4f(&out[node * 128 + cb], make_float4(r[0], r[1], r[2], r[3]));
        stg_stream4f(&out[node * 128 + cb + 4], make_float4(r[4], r[5], r[6], r[7]));
    }
}

// ---------------------------------------------------------------------------
extern "C" void kernel_launch(void* const* d_in, const int* in_sizes, int n_in,
                              void* d_out, int out_size)
{
    const float* x         = (const float*)d_in[0];
    const float* edge_attr = (const float*)d_in[1];
    const int*   edge_idx  = (const int*)  d_in[2];
    const float* Wq = (const float*)d_in[3];
    const float* bq = (const float*)d_in[4];
    const float* Wk = (const float*)d_in[5];
    const float* bk = (const float*)d_in[6];
    const float* Wv = (const float*)d_in[7];
    const float* bv = (const float*)d_in[8];
    const float* We = (const float*)d_in[9];
    const float* Ws = (const float*)d_in[10];
    const float* bs = (const float*)d_in[11];
    const float* Wbeta = (const float*)d_in[12];
    float* out = (float*)d_out;

    int n = in_sizes[0] / 128;
    int e = in_sizes[1] / 16;
    const int* row  = edge_idx;      // destination nodes
    const int* colv = edge_idx + e;  // source nodes

    // One-time host-side objects (no device memory; identical work per call)
    static cudaStream_t s2 = nullptr;
    static cudaEvent_t evFork = nullptr, evJoin = nullptr;
    if (s2 == nullptr) {
        cudaStreamCreateWithFlags(&s2, cudaStreamNonBlocking);
        cudaEventCreateWithFlags(&evFork, cudaEventDisableTiming);
        cudaEventCreateWithFlags(&evJoin, cudaEventDisableTiming);
    }

    cudaFuncSetAttribute(proj_mma, cudaFuncAttributeMaxDynamicSharedMemorySize,
                         PROJ_SMEM);

    // prep on the main (legacy) stream
    prep_kernel<<<289 + (MAXN + 255) / 256, 256>>>(Wq, Wk, Wv, Ws, We, bq, Wbeta);

    // fork: fill_buckets on s2 runs concurrently with proj_mma on main stream
    cudaEventRecord(evFork, 0);
    cudaStreamWaitEvent(s2, evFork, 0);
    fill_buckets<<<(e + 255) / 256, 256, 0, s2>>>(row, colv, e);
    cudaEventRecord(evJoin, s2);

    proj_mma<<<(n + 255) / 256, 512, PROJ_SMEM>>>(x, bq, bk, bv, bs, n);

    // join: agg needs both proj (main) and fill (s2)
    cudaStreamWaitEvent(0, evJoin, 0);
    agg_kernel<<<((long long)n * 32 + 255) / 256, 256>>>(edge_attr, out, n);
}